// round 4
// baseline (speedup 1.0000x reference)
#include <cuda_runtime.h>
#include <math.h>
#include <stdint.h>

#define FN 360
#define BGRAPH 128
#define NNODE (FN*BGRAPH)     /* 46080 */
#define NEDGE 1000000
#define CCH 128
#define TRI 64980             /* 360*361/2 */
#define D1 65364              /* TRI + 384 */
#define H1 512
#define H2 256
#define EPSV 1e-5f
#define PADK 136

// ---------------- scratch (static device allocations) ----------------
__device__ __align__(16) float g_dinv[NNODE];
__device__ __align__(16) float g_A[(size_t)BGRAPH*FN*FN];       // 66.4 MB
__device__ __align__(16) float g_h[(size_t)NNODE*CCH];
__device__ __align__(16) float g_xs1[(size_t)NNODE*CCH];
__device__ __align__(16) float g_xs2[(size_t)NNODE*CCH];
__device__ __align__(16) float g_xs3[(size_t)NNODE*CCH];
__device__ __align__(16) float g_z[(size_t)BGRAPH*D1];          // 33.5 MB
__device__ __align__(16) float g_hpool[BGRAPH*384];
__device__ __align__(16) float g_a1[BGRAPH*H1];
__device__ __align__(16) float g_a2[BGRAPH*H2];
__device__ __align__(16) float g_a3[BGRAPH*H2];

// ---------------- graph structure kernels ----------------
__global__ void k_count_deg(const int* __restrict__ dst) {
    int i = blockIdx.x*blockDim.x + threadIdx.x;
    if (i < NEDGE) atomicAdd(&g_dinv[dst[i]], 1.0f);
}
__global__ void k_make_dinv() {
    int i = blockIdx.x*blockDim.x + threadIdx.x;
    if (i < NNODE) g_dinv[i] = rsqrtf(g_dinv[i] + 1.0f);   // +1 self loop
}
__global__ void k_build_A(const int* __restrict__ src, const int* __restrict__ dst) {
    int i = blockIdx.x*blockDim.x + threadIdx.x;
    if (i >= NEDGE) return;
    int d = dst[i], s = src[i];
    int b = d / FN;
    int r = d - b*FN;
    int c = s - b*FN;
    atomicAdd(&g_A[((size_t)b*FN + r)*FN + c], g_dinv[s]*g_dinv[d]);
}
__global__ void k_add_self() {
    int i = blockIdx.x*blockDim.x + threadIdx.x;
    if (i >= NNODE) return;
    int b = i / FN, r = i - b*FN;
    g_A[((size_t)b*FN + r)*FN + r] += g_dinv[i]*g_dinv[i];
}

// ---------------- helpers ----------------
__device__ __forceinline__ uint32_t f2tf(float f) {
    uint32_t u; asm("cvt.rna.tf32.f32 %0, %1;" : "=r"(u) : "f"(f)); return u;
}
__device__ __forceinline__ void mma8(float* c, const uint32_t* a, const uint32_t* b) {
    asm volatile("mma.sync.aligned.m16n8k8.row.col.f32.tf32.tf32.f32 "
        "{%0,%1,%2,%3}, {%4,%5,%6,%7}, {%8,%9}, {%0,%1,%2,%3};"
        : "+f"(c[0]), "+f"(c[1]), "+f"(c[2]), "+f"(c[3])
        : "r"(a[0]), "r"(a[1]), "r"(a[2]), "r"(a[3]), "r"(b[0]), "r"(b[1]));
}
__device__ __forceinline__ float fast_tanh(float x) {
    // tanh(x) = 1 - 2/(exp(2x)+1); exact identity, __expf + fast divide.
    float e = __expf(2.0f * x);
    return 1.0f - __fdividef(2.0f, e + 1.0f);
}

// ---------------- tf32 tensor-core GEMM, double-buffered ----------------
// C = A[M,K] @ B[K,N]; 128x128 block tile, BK=16, 8 warps (2x4), warp tile 64x32.
// ACT: bias + tanh. SPLIT: k-split along blockIdx.z with atomicAdd epilogue.
// Otherwise blockIdx.z = batch index with strides sA/sB/sC.
template<int ACT, int SPLIT>
__global__ __launch_bounds__(256)
void mmak(const float* __restrict__ A, const float* __restrict__ Bm,
          const float* __restrict__ bias, float* __restrict__ C,
          int M, int N, int K, long sA, long sB, long sC, int kchunk)
{
    if (!SPLIT) {
        A  += (long)blockIdx.z * sA;
        Bm += (long)blockIdx.z * sB;
        C  += (long)blockIdx.z * sC;
    }
    int kbeg = 0, kend = K;
    if (SPLIT) { kbeg = blockIdx.z * kchunk; kend = min(K, kbeg + kchunk); }

    __shared__ uint32_t As[2][16][PADK];   // [buf][k][m]
    __shared__ uint32_t Bs[2][16][PADK];   // [buf][k][n]

    const int tid  = threadIdx.x;
    const int lane = tid & 31;
    const int w    = tid >> 5;
    const int wm   = (w & 1) * 64;
    const int wn   = (w >> 1) * 32;
    const int g    = lane >> 2;     // 0..7
    const int kt   = lane & 3;      // 0..3
    const int rowBase = blockIdx.x * 128;
    const int colBase = blockIdx.y * 128;

    const int aRow = tid >> 1;              // 0..127
    const int aCol = (tid & 1) * 8;         // 0 or 8
    const int bRow = tid >> 4;              // 0..15
    const int bCol = (tid & 15) * 8;        // 0..120

    float acc[4][4][4];
    #pragma unroll
    for (int mi = 0; mi < 4; mi++)
        #pragma unroll
        for (int nj = 0; nj < 4; nj++)
            #pragma unroll
            for (int r = 0; r < 4; r++) acc[mi][nj][r] = 0.f;

    const int gmA = rowBase + aRow;
    float4 pa[2], pb[2];

    // ---- tile loaders (global -> regs) ----
    auto loadTiles = [&](int k0) {
        #pragma unroll
        for (int h = 0; h < 2; h++) {
            int gk = k0 + aCol + h*4;
            float4 v = make_float4(0.f,0.f,0.f,0.f);
            if (gmA < M) {
                if (gk + 3 < kend) {
                    v = *(const float4*)(A + (long)gmA*K + gk);
                } else {
                    if (gk+0 < kend) v.x = A[(long)gmA*K + gk + 0];
                    if (gk+1 < kend) v.y = A[(long)gmA*K + gk + 1];
                    if (gk+2 < kend) v.z = A[(long)gmA*K + gk + 2];
                    if (gk+3 < kend) v.w = A[(long)gmA*K + gk + 3];
                }
            }
            pa[h] = v;
        }
        int gk = k0 + bRow;
        #pragma unroll
        for (int h = 0; h < 2; h++) {
            int gn = colBase + bCol + h*4;
            float4 v = make_float4(0.f,0.f,0.f,0.f);
            if (gk < kend && gn < N) v = *(const float4*)(Bm + (long)gk*N + gn);
            pb[h] = v;
        }
    };
    // ---- regs -> smem (with tf32 convert) ----
    auto storeTiles = [&](int buf) {
        #pragma unroll
        for (int h = 0; h < 2; h++) {
            As[buf][aCol+h*4+0][aRow] = f2tf(pa[h].x);
            As[buf][aCol+h*4+1][aRow] = f2tf(pa[h].y);
            As[buf][aCol+h*4+2][aRow] = f2tf(pa[h].z);
            As[buf][aCol+h*4+3][aRow] = f2tf(pa[h].w);
            Bs[buf][bRow][bCol+h*4+0] = f2tf(pb[h].x);
            Bs[buf][bRow][bCol+h*4+1] = f2tf(pb[h].y);
            Bs[buf][bRow][bCol+h*4+2] = f2tf(pb[h].z);
            Bs[buf][bRow][bCol+h*4+3] = f2tf(pb[h].w);
        }
    };
    // ---- compute one 16-deep k-tile from smem ----
    auto compute = [&](int buf) {
        #pragma unroll
        for (int ks = 0; ks < 2; ks++) {
            uint32_t af[4][4], bf[4][2];
            #pragma unroll
            for (int mi = 0; mi < 4; mi++) {
                int m = wm + mi*16;
                af[mi][0] = As[buf][ks*8 + kt    ][m + g    ];
                af[mi][1] = As[buf][ks*8 + kt    ][m + g + 8];
                af[mi][2] = As[buf][ks*8 + kt + 4][m + g    ];
                af[mi][3] = As[buf][ks*8 + kt + 4][m + g + 8];
            }
            #pragma unroll
            for (int nj = 0; nj < 4; nj++) {
                int n = wn + nj*8;
                bf[nj][0] = Bs[buf][ks*8 + kt    ][n + g];
                bf[nj][1] = Bs[buf][ks*8 + kt + 4][n + g];
            }
            #pragma unroll
            for (int mi = 0; mi < 4; mi++)
                #pragma unroll
                for (int nj = 0; nj < 4; nj++)
                    mma8(acc[mi][nj], af[mi], bf[nj]);
        }
    };

    const int nIter = (kend - kbeg + 15) >> 4;
    loadTiles(kbeg);
    storeTiles(0);
    __syncthreads();
    for (int t = 1; t < nIter; t++) {
        loadTiles(kbeg + t*16);     // LDG in flight during compute below
        compute((t-1) & 1);
        storeTiles(t & 1);
        __syncthreads();
    }
    compute((nIter-1) & 1);

    // --- epilogue ---
    #pragma unroll
    for (int mi = 0; mi < 4; mi++) {
        #pragma unroll
        for (int nj = 0; nj < 4; nj++) {
            #pragma unroll
            for (int r = 0; r < 4; r++) {
                int gm = rowBase + wm + mi*16 + g + (r >> 1)*8;
                int gn = colBase + wn + nj*8 + kt*2 + (r & 1);
                if (gm < M && gn < N) {
                    float v = acc[mi][nj][r];
                    if (SPLIT) {
                        atomicAdd(&C[(long)gm*N + gn], v);
                    } else {
                        if (bias) v += bias[gn];
                        if (ACT) v = fast_tanh(v);
                        C[(long)gm*N + gn] = v;
                    }
                }
            }
        }
    }
}

// ---------------- x0 (upper-triangular) gather + BN into z[:, 0:TRI] --------
__global__ void k_x0_bn(const float* __restrict__ x, const float* __restrict__ g,
                        const float* __restrict__ be, float* __restrict__ z)
{
    int r = blockIdx.x;               // 0..359
    int c = r + threadIdx.x;
    if (c >= FN) return;
    long j = (long)r*FN - (long)r*(r-1)/2 + (c - r);
    float s = 0.f, ss = 0.f;
    for (int b = 0; b < BGRAPH; b++) {
        float v = x[((long)(b*FN + r))*FN + c];
        s += v; ss += v*v;
    }
    float m = s * (1.f/BGRAPH);
    float var = ss * (1.f/BGRAPH) - m*m;
    float sc = rsqrtf(var + EPSV) * g[j];
    float bb = be[j];
    for (int b = 0; b < BGRAPH; b++) {
        float v = x[((long)(b*FN + r))*FN + c];
        z[(long)b*D1 + j] = (v - m)*sc + bb;
    }
}

// ---------------- per-graph mean pooling of the 3 GCN outputs ----------------
__global__ void k_pool(const float* __restrict__ x1, const float* __restrict__ x2,
                       const float* __restrict__ x3, float* __restrict__ hp)
{
    int b = blockIdx.x, l = blockIdx.y, k = threadIdx.x;
    const float* base = (l == 0 ? x1 : l == 1 ? x2 : x3) + (long)b*FN*CCH + k;
    float s0 = 0.f, s1 = 0.f, s2 = 0.f, s3 = 0.f;
    #pragma unroll 1
    for (int n = 0; n < FN; n += 4) {
        s0 += base[(long)(n+0)*CCH];
        s1 += base[(long)(n+1)*CCH];
        s2 += base[(long)(n+2)*CCH];
        s3 += base[(long)(n+3)*CCH];
    }
    hp[b*384 + l*CCH + k] = (s0+s1+s2+s3) * (1.0f/FN);
}

// ---------------- BN of pooled features into z[:, TRI:D1] ----------------
__global__ void k_bn_pool(const float* __restrict__ hp, const float* __restrict__ g,
                          const float* __restrict__ be, float* __restrict__ z)
{
    int j = blockIdx.x*blockDim.x + threadIdx.x;
    if (j >= 384) return;
    float s = 0.f, ss = 0.f;
    for (int b = 0; b < BGRAPH; b++) { float v = hp[b*384 + j]; s += v; ss += v*v; }
    float m = s * (1.f/BGRAPH);
    float var = ss * (1.f/BGRAPH) - m*m;
    float sc = rsqrtf(var + EPSV) * g[j];
    float bb = be[j];
    for (int b = 0; b < BGRAPH; b++)
        z[(long)b*D1 + TRI + j] = (hp[b*384 + j] - m)*sc + bb;
}

// ---------------- column BN (+bias) + ReLU, 128 rows ----------------
__global__ void k_bn_relu(const float* __restrict__ X, const float* __restrict__ bias,
                          const float* __restrict__ gam, const float* __restrict__ bet,
                          float* __restrict__ Y, int ncols)
{
    int col = blockIdx.x;
    int t = threadIdx.x;   // 0..127 = row
    float v = X[t*ncols + col] + bias[col];
    float s = v, ss = v*v;
    #pragma unroll
    for (int o = 16; o > 0; o >>= 1) {
        s  += __shfl_down_sync(0xffffffffu, s,  o);
        ss += __shfl_down_sync(0xffffffffu, ss, o);
    }
    __shared__ float ws[4], wss[4];
    __shared__ float sm, sscale;
    int wid = t >> 5, lane = t & 31;
    if (lane == 0) { ws[wid] = s; wss[wid] = ss; }
    __syncthreads();
    if (t == 0) {
        float S = ws[0]+ws[1]+ws[2]+ws[3];
        float SS = wss[0]+wss[1]+wss[2]+wss[3];
        float m = S * (1.f/BGRAPH);
        float var = SS * (1.f/BGRAPH) - m*m;
        sm = m; sscale = rsqrtf(var + EPSV);
    }
    __syncthreads();
    float o = (v - sm) * sscale * gam[col] + bet[col];
    Y[t*ncols + col] = fmaxf(o, 0.f);
}

// ---------------- final linear + log_softmax ----------------
__global__ void k_head(const float* __restrict__ a3, const float* __restrict__ W4,
                       const float* __restrict__ b4, float* __restrict__ out)
{
    int b = blockIdx.x, lane = threadIdx.x;
    float s0 = 0.f, s1 = 0.f;
    for (int i = lane; i < H2; i += 32) {
        float v = a3[b*H2 + i];
        s0 = fmaf(v, W4[i*2 + 0], s0);
        s1 = fmaf(v, W4[i*2 + 1], s1);
    }
    #pragma unroll
    for (int o = 16; o > 0; o >>= 1) {
        s0 += __shfl_down_sync(0xffffffffu, s0, o);
        s1 += __shfl_down_sync(0xffffffffu, s1, o);
    }
    if (lane == 0) {
        float l0 = s0 + b4[0], l1 = s1 + b4[1];
        float m = fmaxf(l0, l1);
        float lse = m + logf(expf(l0 - m) + expf(l1 - m));
        out[b*2 + 0] = l0 - lse;
        out[b*2 + 1] = l1 - lse;
    }
}

// ---------------- launch ----------------
extern "C" void kernel_launch(void* const* d_in, const int* in_sizes, int n_in,
                              void* d_out, int out_size)
{
    const float* x    = (const float*)d_in[0];
    const int*   esrc = (const int*)d_in[1];
    const int*   edst = (const int*)d_in[2];
    const float* Wc1  = (const float*)d_in[4];
    const float* bc1  = (const float*)d_in[5];
    const float* Wc2  = (const float*)d_in[6];
    const float* bc2  = (const float*)d_in[7];
    const float* Wc3  = (const float*)d_in[8];
    const float* bc3  = (const float*)d_in[9];
    const float* bn_g = (const float*)d_in[10];
    const float* bn_b = (const float*)d_in[11];
    const float* bnh_g= (const float*)d_in[12];
    const float* bnh_b= (const float*)d_in[13];
    const float* W1   = (const float*)d_in[14];
    const float* b1   = (const float*)d_in[15];
    const float* g1   = (const float*)d_in[16];
    const float* be1  = (const float*)d_in[17];
    const float* W2   = (const float*)d_in[18];
    const float* b2   = (const float*)d_in[19];
    const float* g2   = (const float*)d_in[20];
    const float* be2  = (const float*)d_in[21];
    const float* W3   = (const float*)d_in[22];
    const float* b3   = (const float*)d_in[23];
    const float* g3   = (const float*)d_in[24];
    const float* be3  = (const float*)d_in[25];
    const float* W4   = (const float*)d_in[26];
    const float* b4   = (const float*)d_in[27];
    float* out = (float*)d_out;

    void *pDinv, *pA, *pH, *pX1, *pX2, *pX3, *pZ, *pHp, *pA1, *pA2, *pA3;
    cudaGetSymbolAddress(&pDinv, g_dinv);
    cudaGetSymbolAddress(&pA,  g_A);
    cudaGetSymbolAddress(&pH,  g_h);
    cudaGetSymbolAddress(&pX1, g_xs1);
    cudaGetSymbolAddress(&pX2, g_xs2);
    cudaGetSymbolAddress(&pX3, g_xs3);
    cudaGetSymbolAddress(&pZ,  g_z);
    cudaGetSymbolAddress(&pHp, g_hpool);
    cudaGetSymbolAddress(&pA1, g_a1);
    cudaGetSymbolAddress(&pA2, g_a2);
    cudaGetSymbolAddress(&pA3, g_a3);

    // 1) degrees -> dinv
    cudaMemsetAsync(pDinv, 0, (size_t)NNODE*sizeof(float), 0);
    k_count_deg<<<(NEDGE+255)/256, 256>>>(edst);
    k_make_dinv<<<(NNODE+255)/256, 256>>>();

    // 2) dense normalized adjacency (shared by all 3 layers)
    cudaMemsetAsync(pA, 0, (size_t)BGRAPH*FN*FN*sizeof(float), 0);
    k_build_A<<<(NEDGE+255)/256, 256>>>(esrc, edst);
    k_add_self<<<(NNODE+255)/256, 256>>>();

    const long sAb = (long)FN*FN;      // per-graph adjacency stride
    const long sHb = (long)FN*CCH;     // per-graph feature stride

    // 3) GCN layer 1: h = x @ Wc1 ; xs1 = tanh(A @ h + bc1)
    mmak<0,0><<<dim3(360,1,1), 256>>>(x, Wc1, nullptr, (float*)pH,
                                      NNODE, CCH, FN, 0,0,0, 0);
    mmak<1,0><<<dim3(3,1,BGRAPH), 256>>>((const float*)pA, (const float*)pH, bc1, (float*)pX1,
                                         FN, CCH, FN, sAb, sHb, sHb, 0);
    // 4) layer 2
    mmak<0,0><<<dim3(360,1,1), 256>>>((const float*)pX1, Wc2, nullptr, (float*)pH,
                                      NNODE, CCH, CCH, 0,0,0, 0);
    mmak<1,0><<<dim3(3,1,BGRAPH), 256>>>((const float*)pA, (const float*)pH, bc2, (float*)pX2,
                                         FN, CCH, FN, sAb, sHb, sHb, 0);
    // 5) layer 3
    mmak<0,0><<<dim3(360,1,1), 256>>>((const float*)pX2, Wc3, nullptr, (float*)pH,
                                      NNODE, CCH, CCH, 0,0,0, 0);
    mmak<1,0><<<dim3(3,1,BGRAPH), 256>>>((const float*)pA, (const float*)pH, bc3, (float*)pX3,
                                         FN, CCH, FN, sAb, sHb, sHb, 0);

    // 6) z = [ BN(triu(x)) | BN(pool(xs1..3)) ]
    k_x0_bn<<<FN, 384>>>(x, bn_g, bn_b, (float*)pZ);
    k_pool<<<dim3(BGRAPH,3), CCH>>>((const float*)pX1, (const float*)pX2, (const float*)pX3, (float*)pHp);
    k_bn_pool<<<3, 128>>>((const float*)pHp, bnh_g, bnh_b, (float*)pZ);

    // 7) a1 = relu(BN(z @ W1 + b1))   (tf32 split-K, fp32 atomics)
    cudaMemsetAsync(pA1, 0, (size_t)BGRAPH*H1*sizeof(float), 0);
    mmak<0,1><<<dim3(1,4,64), 256>>>((const float*)pZ, W1, nullptr, (float*)pA1,
                                     BGRAPH, H1, D1, 0,0,0, 1024);
    k_bn_relu<<<H1, 128>>>((const float*)pA1, b1, g1, be1, (float*)pA1, H1);

    // 8) a2 = relu(BN(a1 @ W2 + b2))
    mmak<0,0><<<dim3(1,2,1), 256>>>((const float*)pA1, W2, nullptr, (float*)pA2,
                                    BGRAPH, H2, H1, 0,0,0, 0);
    k_bn_relu<<<H2, 128>>>((const float*)pA2, b2, g2, be2, (float*)pA2, H2);

    // 9) a3 = relu(BN(a2 @ W3 + b3))
    mmak<0,0><<<dim3(1,2,1), 256>>>((const float*)pA2, W3, nullptr, (float*)pA3,
                                    BGRAPH, H2, H2, 0,0,0, 0);
    k_bn_relu<<<H2, 128>>>((const float*)pA3, b3, g3, be3, (float*)pA3, H2);

    // 10) logits + log_softmax
    k_head<<<BGRAPH, 32>>>((const float*)pA3, W4, b4, out);
}

// round 8
// speedup vs baseline: 1.0485x; 1.0485x over previous
#include <cuda_runtime.h>
#include <math.h>
#include <stdint.h>

#define FN 360
#define BGRAPH 128
#define NNODE (FN*BGRAPH)
#define NEDGE 1000000
#define CCH 128
#define TRI 64980
#define D1 65364
#define ZP 65376
#define H1 512
#define H2 256
#define EPSV 1e-5f
#define PADK 136
#define AP 384

// ---------------- scratch ----------------
__device__ __align__(16) float g_dinv[NNODE];
__device__ __align__(16) float g_A[(size_t)BGRAPH*AP*AP];
__device__ __align__(16) float g_xr[(size_t)NNODE*AP];
__device__ __align__(16) float g_wr[(size_t)3*AP*CCH];
__device__ __align__(16) float g_h[(size_t)BGRAPH*AP*CCH];
__device__ __align__(16) float g_xs1[(size_t)NNODE*CCH];
__device__ __align__(16) float g_xs2[(size_t)NNODE*CCH];
__device__ __align__(16) float g_xs3[(size_t)NNODE*CCH];
__device__ __align__(16) float g_z[(size_t)BGRAPH*ZP];
__device__ __align__(16) float g_hpool[BGRAPH*384];
__device__ __align__(16) float g_a1[BGRAPH*H1];
__device__ __align__(16) float g_a2[BGRAPH*H2];
__device__ __align__(16) float g_a3[BGRAPH*H2];

// ---------------- helpers ----------------
__device__ __forceinline__ uint32_t f2tf(float f) {
    uint32_t u; asm("cvt.rna.tf32.f32 %0, %1;" : "=r"(u) : "f"(f)); return u;
}
__device__ __forceinline__ float rndtf(float f) { return __uint_as_float(f2tf(f)); }
__device__ __forceinline__ float fast_tanh(float x) {
    float e = __expf(2.0f*x);
    return 1.0f - __fdividef(2.0f, e + 1.0f);
}
__device__ __forceinline__ uint32_t s2u(const void* p) {
    uint32_t a;
    asm("{ .reg .u64 t; cvta.to.shared.u64 t, %1; cvt.u32.u64 %0, t; }" : "=r"(a) : "l"(p));
    return a;
}
__device__ __forceinline__ void cpa16(uint32_t d, const void* g) {
    asm volatile("cp.async.cg.shared.global [%0], [%1], 16;" :: "r"(d), "l"(g));
}
__device__ __forceinline__ void mma8(float* c, const uint32_t* a, const uint32_t* b) {
    asm volatile("mma.sync.aligned.m16n8k8.row.col.f32.tf32.tf32.f32 "
        "{%0,%1,%2,%3}, {%4,%5,%6,%7}, {%8,%9}, {%0,%1,%2,%3};"
        : "+f"(c[0]), "+f"(c[1]), "+f"(c[2]), "+f"(c[3])
        : "r"(a[0]), "r"(a[1]), "r"(a[2]), "r"(a[3]), "r"(b[0]), "r"(b[1]));
}

// ---------------- prep ----------------
__global__ void k_prep(const float* __restrict__ Wc1, const float* __restrict__ Wc2,
                       const float* __restrict__ Wc3) {
    int i = blockIdx.x*blockDim.x + threadIdx.x;
    if (i >= 3*AP*CCH) return;
    int w = i / (AP*CCH);
    int k = (i / CCH) % AP;
    int r = i % CCH;
    const float* W = (w==0) ? Wc1 : (w==1) ? Wc2 : Wc3;
    int KW = (w==0) ? FN : CCH;
    g_wr[i] = (k < KW) ? rndtf(W[k*CCH + r]) : 0.f;
}
__global__ void k_xr(const float* __restrict__ x) {
    int i = blockIdx.x*blockDim.x + threadIdx.x;
    if (i >= NNODE*(AP/4)) return;
    int n = i / (AP/4), k4 = i % (AP/4);
    float4 o = make_float4(0.f,0.f,0.f,0.f);
    if (k4*4 < FN) {
        float4 v = *(const float4*)(x + (size_t)n*FN + k4*4);
        o.x = rndtf(v.x); o.y = rndtf(v.y); o.z = rndtf(v.z); o.w = rndtf(v.w);
    }
    *(float4*)(g_xr + (size_t)n*AP + k4*4) = o;
}
__global__ void k_count_deg(const int* __restrict__ dst) {
    int i = blockIdx.x*blockDim.x + threadIdx.x;
    if (i < NEDGE) atomicAdd(&g_dinv[dst[i]], 1.0f);
}
__global__ void k_make_dinv() {
    int i = blockIdx.x*blockDim.x + threadIdx.x;
    if (i < NNODE) g_dinv[i] = rsqrtf(g_dinv[i] + 1.0f);
}
__global__ void k_build(const int* __restrict__ src, const int* __restrict__ dst) {
    int i = blockIdx.x*blockDim.x + threadIdx.x;
    if (i < NEDGE) {
        int d = dst[i], s = src[i];
        int b = d / FN, r = d - b*FN, c = s - b*FN;
        atomicAdd(&g_A[((size_t)b*AP + r)*AP + c], g_dinv[s]*g_dinv[d]);
    } else if (i < NEDGE + NNODE) {
        int n = i - NEDGE, b = n / FN, r = n - b*FN;
        atomicAdd(&g_A[((size_t)b*AP + r)*AP + r], g_dinv[n]*g_dinv[n]);
    }
}
__global__ void k_round_A() {
    size_t stride = (size_t)gridDim.x*blockDim.x;
    size_t tot = (size_t)BGRAPH*AP*AP/4;
    for (size_t i = blockIdx.x*blockDim.x + threadIdx.x; i < tot; i += stride) {
        float4 v = *(float4*)(g_A + i*4);
        v.x = rndtf(v.x); v.y = rndtf(v.y); v.z = rndtf(v.z); v.w = rndtf(v.w);
        *(float4*)(g_A + i*4) = v;
    }
}

// ---------------- tf32 HMMA GEMM, cp.async pipelined, pre-rounded operands ----
// 128x128 tile, BK=32, 256 thr (8 warps 2x4, warp 64x32).
// MODE 0: XW -> g_h[(b*AP+j)*CCH+c] rounded. grid(360)
// MODE 1: AH -> xs = rndtf(tanh(D+bias)). grid(3, BGRAPH); blockIdx.y = GRAPH,
//         so colBase MUST be 0 (N = 128 exactly).
// MODE 2: split-K atomicAdd into Cg[M x H1]; B rows clamped to KREAL-1
//         (A cols >= KREAL are zero pad, so clamped-row garbage * 0 = 0).
template<int MODE>
__global__ __launch_bounds__(256)
void gk(const float* __restrict__ Ag, const float* __restrict__ Bg,
        const float* __restrict__ bias, float* __restrict__ Cg,
        int lda, int ldb, int M, int K, int KREAL, int kchunk)
{
    extern __shared__ __align__(16) float dyn[];
    const int tid = threadIdx.x, lane = tid & 31, w = tid >> 5;
    const int wm = (w & 1)*64, wn = (w >> 1)*32;
    const int g = lane >> 2, kt = lane & 3;
    const int rowBase = blockIdx.x*128;
    const int colBase = (MODE == 1) ? 0 : blockIdx.y*128;   // R7 FIX: MODE1 y = graph

    if (MODE == 1) {
        Ag += (size_t)blockIdx.y * AP * AP;
        Bg += (size_t)blockIdx.y * AP * CCH;
    }
    int kbeg = 0, kend = K;
    if (MODE == 2) { kbeg = blockIdx.z*kchunk; kend = min(K, kbeg + kchunk); }

    const int STG = 8832;                 // floats/stage: A 128x36 + B 32x132
    const int am = tid >> 1;              // A row, 2 threads/row
    const int ak = (tid & 1) * 16;        // A col block (16 floats)
    const int bk = tid >> 3;              // B row 0..31
    const int bn = (tid & 7) * 16;        // B col block (16 floats)

    auto load_chunk = [&](int c, int stg) {
        int k0 = kbeg + c*32;
        float* As = dyn + stg*STG;
        float* Bs = As + 4608;
        const float* ar = Ag + (size_t)(rowBase + am)*lda + k0 + ak;
        uint32_t ad = s2u(As + am*36 + ak);
        cpa16(ad,      ar);
        cpa16(ad + 16, ar + 4);
        cpa16(ad + 32, ar + 8);
        cpa16(ad + 48, ar + 12);
        int kg = k0 + bk;
        if (MODE == 2) kg = min(kg, KREAL - 1);
        const float* br = Bg + (size_t)kg*ldb + colBase + bn;
        uint32_t bd = s2u(Bs + bk*132 + bn);
        cpa16(bd,      br);
        cpa16(bd + 16, br + 4);
        cpa16(bd + 32, br + 8);
        cpa16(bd + 48, br + 12);
        asm volatile("cp.async.commit_group;" ::: "memory");
    };

    float acc[4][4][4];
    #pragma unroll
    for (int mi = 0; mi < 4; mi++)
        #pragma unroll
        for (int nj = 0; nj < 4; nj++)
            #pragma unroll
            for (int r = 0; r < 4; r++) acc[mi][nj][r] = 0.f;

    const int nch = (kend - kbeg) >> 5;
    load_chunk(0, 0);
    for (int c = 0; c < nch; c++) {
        int buf = c & 1;
        if (c + 1 < nch) {
            load_chunk(c + 1, buf ^ 1);
            asm volatile("cp.async.wait_group 1;" ::: "memory");
        } else {
            asm volatile("cp.async.wait_group 0;" ::: "memory");
        }
        __syncthreads();
        const float* As = dyn + buf*STG;
        const float* Bs = As + 4608;
        #pragma unroll
        for (int ks = 0; ks < 4; ks++) {
            uint32_t af[4][4], bf[4][2];
            #pragma unroll
            for (int mi = 0; mi < 4; mi++) {
                int m = wm + mi*16 + g;
                af[mi][0] = __float_as_uint(As[(m    )*36 + ks*8 + kt    ]);
                af[mi][1] = __float_as_uint(As[(m + 8)*36 + ks*8 + kt    ]);
                af[mi][2] = __float_as_uint(As[(m    )*36 + ks*8 + kt + 4]);
                af[mi][3] = __float_as_uint(As[(m + 8)*36 + ks*8 + kt + 4]);
            }
            #pragma unroll
            for (int nj = 0; nj < 4; nj++) {
                int n = wn + nj*8 + g;
                bf[nj][0] = __float_as_uint(Bs[(ks*8 + kt    )*132 + n]);
                bf[nj][1] = __float_as_uint(Bs[(ks*8 + kt + 4)*132 + n]);
            }
            #pragma unroll
            for (int mi = 0; mi < 4; mi++)
                #pragma unroll
                for (int nj = 0; nj < 4; nj++)
                    mma8(acc[mi][nj], af[mi], bf[nj]);
        }
        __syncthreads();
    }

    #pragma unroll
    for (int mi = 0; mi < 4; mi++)
        #pragma unroll
        for (int nj = 0; nj < 4; nj++)
            #pragma unroll
            for (int r = 0; r < 4; r++) {
                int gm = rowBase + wm + mi*16 + g + (r>>1)*8;
                int gn = colBase + wn + nj*8 + kt*2 + (r&1);
                float v = acc[mi][nj][r];
                if (MODE == 0) {
                    int b = gm / FN, j = gm - b*FN;
                    g_h[((size_t)b*AP + j)*CCH + gn] = rndtf(v);
                } else if (MODE == 1) {
                    if (gm < M) {
                        float* dst = Cg + ((size_t)blockIdx.y*FN + gm)*CCH;
                        dst[gn] = rndtf(fast_tanh(v + __ldg(bias + gn)));
                    }
                } else {
                    atomicAdd(&Cg[(size_t)gm*H1 + gn], v);
                }
            }
}

// ---------------- legacy tf32 mma.sync GEMM (small MLP layers) ----------------
__global__ __launch_bounds__(256)
void mmak(const float* __restrict__ A, const float* __restrict__ Bm,
          float* __restrict__ C, int M, int N, int K)
{
    __shared__ uint32_t As[2][16][PADK];
    __shared__ uint32_t Bs[2][16][PADK];
    const int tid = threadIdx.x, lane = tid & 31, w = tid >> 5;
    const int wm = (w & 1)*64, wn = (w >> 1)*32;
    const int g = lane >> 2, kt = lane & 3;
    const int rowBase = blockIdx.x*128, colBase = blockIdx.y*128;
    const int aRow = tid >> 1, aCol = (tid & 1)*8;
    const int bRow = tid >> 4, bCol = (tid & 15)*8;
    float acc[4][4][4];
    #pragma unroll
    for (int mi = 0; mi < 4; mi++)
        #pragma unroll
        for (int nj = 0; nj < 4; nj++)
            #pragma unroll
            for (int r = 0; r < 4; r++) acc[mi][nj][r] = 0.f;
    const int gmA = rowBase + aRow;
    float4 pa[2], pb[2];
    auto loadT = [&](int k0) {
        #pragma unroll
        for (int h = 0; h < 2; h++) {
            int gk = k0 + aCol + h*4;
            float4 v = make_float4(0.f,0.f,0.f,0.f);
            if (gmA < M && gk + 3 < K) v = *(const float4*)(A + (size_t)gmA*K + gk);
            pa[h] = v;
        }
        int gk = k0 + bRow;
        #pragma unroll
        for (int h = 0; h < 2; h++) {
            int gn = colBase + bCol + h*4;
            float4 v = make_float4(0.f,0.f,0.f,0.f);
            if (gk < K && gn < N) v = *(const float4*)(Bm + (size_t)gk*N + gn);
            pb[h] = v;
        }
    };
    auto storeT = [&](int buf) {
        #pragma unroll
        for (int h = 0; h < 2; h++) {
            As[buf][aCol+h*4+0][aRow] = f2tf(pa[h].x);
            As[buf][aCol+h*4+1][aRow] = f2tf(pa[h].y);
            As[buf][aCol+h*4+2][aRow] = f2tf(pa[h].z);
            As[buf][aCol+h*4+3][aRow] = f2tf(pa[h].w);
            Bs[buf][bRow][bCol+h*4+0] = f2tf(pb[h].x);
            Bs[buf][bRow][bCol+h*4+1] = f2tf(pb[h].y);
            Bs[buf][bRow][bCol+h*4+2] = f2tf(pb[h].z);
            Bs[buf][bRow][bCol+h*4+3] = f2tf(pb[h].w);
        }
    };
    auto comp = [&](int buf) {
        #pragma unroll
        for (int ks = 0; ks < 2; ks++) {
            uint32_t af[4][4], bf[4][2];
            #pragma unroll
            for (int mi = 0; mi < 4; mi++) {
                int m = wm + mi*16;
                af[mi][0] = As[buf][ks*8+kt  ][m+g  ];
                af[mi][1] = As[buf][ks*8+kt  ][m+g+8];
                af[mi][2] = As[buf][ks*8+kt+4][m+g  ];
                af[mi][3] = As[buf][ks*8+kt+4][m+g+8];
            }
            #pragma unroll
            for (int nj = 0; nj < 4; nj++) {
                int n = wn + nj*8;
                bf[nj][0] = Bs[buf][ks*8+kt  ][n+g];
                bf[nj][1] = Bs[buf][ks*8+kt+4][n+g];
            }
            #pragma unroll
            for (int mi = 0; mi < 4; mi++)
                #pragma unroll
                for (int nj = 0; nj < 4; nj++) mma8(acc[mi][nj], af[mi], bf[nj]);
        }
    };
    const int nIter = (K + 15) >> 4;
    loadT(0); storeT(0); __syncthreads();
    for (int t = 1; t < nIter; t++) {
        loadT(t*16);
        comp((t-1) & 1);
        storeT(t & 1);
        __syncthreads();
    }
    comp((nIter-1) & 1);
    #pragma unroll
    for (int mi = 0; mi < 4; mi++)
        #pragma unroll
        for (int nj = 0; nj < 4; nj++)
            #pragma unroll
            for (int r = 0; r < 4; r++) {
                int gm = rowBase + wm + mi*16 + g + (r>>1)*8;
                int gn = colBase + wn + nj*8 + kt*2 + (r&1);
                if (gm < M && gn < N) C[(size_t)gm*N + gn] = acc[mi][nj][r];
            }
}

// ---------------- BN / pool / head ----------------
__global__ void k_x0_bn(const float* __restrict__ x, const float* __restrict__ g,
                        const float* __restrict__ be, float* __restrict__ z)
{
    int r = blockIdx.x;
    int c = r + threadIdx.x;
    if (c >= FN) return;
    long j = (long)r*FN - (long)r*(r-1)/2 + (c - r);
    float s = 0.f, ss = 0.f;
    for (int b = 0; b < BGRAPH; b++) {
        float v = x[((size_t)(b*FN + r))*FN + c];
        s += v; ss += v*v;
    }
    float m = s*(1.f/BGRAPH);
    float var = ss*(1.f/BGRAPH) - m*m;
    float sc = rsqrtf(var + EPSV)*g[j];
    float bb = be[j];
    for (int b = 0; b < BGRAPH; b++) {
        float v = x[((size_t)(b*FN + r))*FN + c];
        z[(size_t)b*ZP + j] = rndtf((v - m)*sc + bb);
    }
}
__global__ void k_pool(const float* __restrict__ x1, const float* __restrict__ x2,
                       const float* __restrict__ x3, float* __restrict__ hp)
{
    int b = blockIdx.x, l = blockIdx.y, k = threadIdx.x;
    const float* base = (l==0 ? x1 : l==1 ? x2 : x3) + (size_t)b*FN*CCH + k;
    float s0=0.f, s1=0.f, s2=0.f, s3=0.f;
    #pragma unroll 1
    for (int n = 0; n < FN; n += 4) {
        s0 += base[(size_t)(n+0)*CCH];
        s1 += base[(size_t)(n+1)*CCH];
        s2 += base[(size_t)(n+2)*CCH];
        s3 += base[(size_t)(n+3)*CCH];
    }
    hp[b*384 + l*CCH + k] = (s0+s1+s2+s3)*(1.0f/FN);
}
__global__ void k_bn_pool(const float* __restrict__ hp, const float* __restrict__ g,
                          const float* __restrict__ be, float* __restrict__ z)
{
    int j = blockIdx.x*blockDim.x + threadIdx.x;
    if (j >= 396) return;
    if (j >= 384) {   // zero z pad columns (needed by clamped W1 tail)
        for (int b = 0; b < BGRAPH; b++) z[(size_t)b*ZP + TRI + j] = 0.f;
        return;
    }
    float s = 0.f, ss = 0.f;
    for (int b = 0; b < BGRAPH; b++) { float v = hp[b*384 + j]; s += v; ss += v*v; }
    float m = s*(1.f/BGRAPH);
    float var = ss*(1.f/BGRAPH) - m*m;
    float sc = rsqrtf(var + EPSV)*g[j];
    float bb = be[j];
    for (int b = 0; b < BGRAPH; b++)
        z[(size_t)b*ZP + TRI + j] = rndtf((hp[b*384 + j] - m)*sc + bb);
}
__global__ void k_bn_relu(const float* __restrict__ X, const float* __restrict__ bias,
                          const float* __restrict__ gam, const float* __restrict__ bet,
                          float* __restrict__ Y, int ncols)
{
    int col = blockIdx.x, t = threadIdx.x;
    float v = X[t*ncols + col] + bias[col];
    float s = v, ss = v*v;
    #pragma unroll
    for (int o = 16; o > 0; o >>= 1) {
        s  += __shfl_down_sync(0xffffffffu, s,  o);
        ss += __shfl_down_sync(0xffffffffu, ss, o);
    }
    __shared__ float ws[4], wss[4];
    __shared__ float sm, sscale;
    int wid = t >> 5, lane = t & 31;
    if (lane == 0) { ws[wid] = s; wss[wid] = ss; }
    __syncthreads();
    if (t == 0) {
        float S = ws[0]+ws[1]+ws[2]+ws[3];
        float SS = wss[0]+wss[1]+wss[2]+wss[3];
        float m = S*(1.f/BGRAPH);
        sm = m; sscale = rsqrtf(SS*(1.f/BGRAPH) - m*m + EPSV);
    }
    __syncthreads();
    float o = (v - sm)*sscale*gam[col] + bet[col];
    Y[t*ncols + col] = fmaxf(o, 0.f);
}
__global__ void k_head(const float* __restrict__ a3, const float* __restrict__ W4,
                       const float* __restrict__ b4, float* __restrict__ out)
{
    int b = blockIdx.x, lane = threadIdx.x;
    float s0 = 0.f, s1 = 0.f;
    for (int i = lane; i < H2; i += 32) {
        float v = a3[b*H2 + i];
        s0 = fmaf(v, W4[i*2+0], s0);
        s1 = fmaf(v, W4[i*2+1], s1);
    }
    #pragma unroll
    for (int o = 16; o > 0; o >>= 1) {
        s0 += __shfl_down_sync(0xffffffffu, s0, o);
        s1 += __shfl_down_sync(0xffffffffu, s1, o);
    }
    if (lane == 0) {
        float l0 = s0 + b4[0], l1 = s1 + b4[1];
        float m = fmaxf(l0, l1);
        float lse = m + logf(expf(l0-m) + expf(l1-m));
        out[b*2+0] = l0 - lse;
        out[b*2+1] = l1 - lse;
    }
}

// ---------------- launch ----------------
extern "C" void kernel_launch(void* const* d_in, const int* in_sizes, int n_in,
                              void* d_out, int out_size)
{
    const float* x    = (const float*)d_in[0];
    const int*   esrc = (const int*)d_in[1];
    const int*   edst = (const int*)d_in[2];
    const float* Wc1  = (const float*)d_in[4];
    const float* bc1  = (const float*)d_in[5];
    const float* Wc2  = (const float*)d_in[6];
    const float* bc2  = (const float*)d_in[7];
    const float* Wc3  = (const float*)d_in[8];
    const float* bc3  = (const float*)d_in[9];
    const float* bn_g = (const float*)d_in[10];
    const float* bn_b = (const float*)d_in[11];
    const float* bnh_g= (const float*)d_in[12];
    const float* bnh_b= (const float*)d_in[13];
    const float* W1   = (const float*)d_in[14];
    const float* b1   = (const float*)d_in[15];
    const float* g1   = (const float*)d_in[16];
    const float* be1  = (const float*)d_in[17];
    const float* W2   = (const float*)d_in[18];
    const float* b2   = (const float*)d_in[19];
    const float* g2   = (const float*)d_in[20];
    const float* be2  = (const float*)d_in[21];
    const float* W3   = (const float*)d_in[22];
    const float* b3   = (const float*)d_in[23];
    const float* g3   = (const float*)d_in[24];
    const float* be3  = (const float*)d_in[25];
    const float* W4   = (const float*)d_in[26];
    const float* b4   = (const float*)d_in[27];
    float* out = (float*)d_out;

    const int DSM = 2*8832*4;
    cudaFuncSetAttribute(gk<0>, cudaFuncAttributeMaxDynamicSharedMemorySize, DSM);
    cudaFuncSetAttribute(gk<1>, cudaFuncAttributeMaxDynamicSharedMemorySize, DSM);
    cudaFuncSetAttribute(gk<2>, cudaFuncAttributeMaxDynamicSharedMemorySize, DSM);

    void *pDinv, *pA, *pXr, *pWr, *pH, *pX1, *pX2, *pX3, *pZ, *pHp, *pA1, *pA2, *pA3;
    cudaGetSymbolAddress(&pDinv, g_dinv);
    cudaGetSymbolAddress(&pA,  g_A);
    cudaGetSymbolAddress(&pXr, g_xr);
    cudaGetSymbolAddress(&pWr, g_wr);
    cudaGetSymbolAddress(&pH,  g_h);
    cudaGetSymbolAddress(&pX1, g_xs1);
    cudaGetSymbolAddress(&pX2, g_xs2);
    cudaGetSymbolAddress(&pX3, g_xs3);
    cudaGetSymbolAddress(&pZ,  g_z);
    cudaGetSymbolAddress(&pHp, g_hpool);
    cudaGetSymbolAddress(&pA1, g_a1);
    cudaGetSymbolAddress(&pA2, g_a2);
    cudaGetSymbolAddress(&pA3, g_a3);

    const float* xr = (const float*)pXr;
    const float* wr = (const float*)pWr;

    cudaMemsetAsync(pDinv, 0, (size_t)NNODE*4, 0);
    cudaMemsetAsync(pA, 0, (size_t)BGRAPH*AP*AP*4, 0);
    cudaMemsetAsync(pH, 0, (size_t)BGRAPH*AP*CCH*4, 0);
    k_prep<<<(3*AP*CCH+255)/256, 256>>>(Wc1, Wc2, Wc3);
    k_xr<<<(NNODE*(AP/4)+255)/256, 256>>>(x);
    k_count_deg<<<(NEDGE+255)/256, 256>>>(edst);
    k_make_dinv<<<(NNODE+255)/256, 256>>>();
    k_build<<<(NEDGE+NNODE+255)/256, 256>>>(esrc, edst);
    k_round_A<<<2048, 256>>>();

    // GCN: h = X@W ; xs = tanh(A@h + b)
    gk<0><<<dim3(360,1), 256, DSM>>>(xr, wr, nullptr, nullptr, AP, CCH, NNODE, AP, AP, 0);
    gk<1><<<dim3(3,BGRAPH), 256, DSM>>>((const float*)pA, (const float*)pH, bc1, (float*)pX1,
                                        AP, CCH, FN, AP, AP, 0);
    gk<0><<<dim3(360,1), 256, DSM>>>((const float*)pX1, wr + (size_t)AP*CCH, nullptr, nullptr,
                                     CCH, CCH, NNODE, CCH, CCH, 0);
    gk<1><<<dim3(3,BGRAPH), 256, DSM>>>((const float*)pA, (const float*)pH, bc2, (float*)pX2,
                                        AP, CCH, FN, AP, AP, 0);
    gk<0><<<dim3(360,1), 256, DSM>>>((const float*)pX2, wr + (size_t)2*AP*CCH, nullptr, nullptr,
                                     CCH, CCH, NNODE, CCH, CCH, 0);
    gk<1><<<dim3(3,BGRAPH), 256, DSM>>>((const float*)pA, (const float*)pH, bc3, (float*)pX3,
                                        AP, CCH, FN, AP, AP, 0);

    // features
    k_x0_bn<<<FN, 384>>>(x, bn_g, bn_b, (float*)pZ);
    k_pool<<<dim3(BGRAPH,3), CCH>>>((const float*)pX1, (const float*)pX2, (const float*)pX3, (float*)pHp);
    k_bn_pool<<<1, 512>>>((const float*)pHp, bnh_g, bnh_b, (float*)pZ);

    // MLP
    cudaMemsetAsync(pA1, 0, (size_t)BGRAPH*H1*4, 0);
    gk<2><<<dim3(1,4,64), 256, DSM>>>((const float*)pZ, W1, nullptr, (float*)pA1,
                                      ZP, H1, BGRAPH, ZP, D1, 1024);
    k_bn_relu<<<H1, 128>>>((const float*)pA1, b1, g1, be1, (float*)pA1, H1);
    mmak<<<dim3(1,2), 256>>>((const float*)pA1, W2, (float*)pA2, BGRAPH, H2, H1);
    k_bn_relu<<<H2, 128>>>((const float*)pA2, b2, g2, be2, (float*)pA2, H2);
    mmak<<<dim3(1,2), 256>>>((const float*)pA2, W3, (float*)pA3, BGRAPH, H2, H2);
    k_bn_relu<<<H2, 128>>>((const float*)pA3, b3, g3, be3, (float*)pA3, H2);
    k_head<<<BGRAPH, 32>>>((const float*)pA3, W4, b4, out);
}